// round 1
// baseline (speedup 1.0000x reference)
#include <cuda_runtime.h>

#define NN 50000
#define EE 800000
#define DD 128
#define BM 128

// ---------------- device scratch (static, allocation-free) ----------------
__device__ float g_self[NN * DD];
__device__ float g_y[NN * DD];
__device__ float g_m[NN * DD];
__device__ float g_z[NN * DD];
__device__ int g_cnt[2][NN];
__device__ int g_off[2][NN + 1];
__device__ int g_cur[2][NN];
__device__ int g_adj[2][EE];

// ---------------- CSR construction ----------------
__global__ void zero_cnt_kernel(int n) {
    int i = blockIdx.x * blockDim.x + threadIdx.x;
    if (i < n) { g_cnt[0][i] = 0; g_cnt[1][i] = 0; }
}

__global__ void hist_kernel(const int* __restrict__ src, const int* __restrict__ dst, int E) {
    int e = blockIdx.x * blockDim.x + threadIdx.x;
    if (e < E) {
        atomicAdd(&g_cnt[0][dst[e]], 1);   // forward: aggregate at dst
        atomicAdd(&g_cnt[1][src[e]], 1);   // backward (reversed graph): aggregate at src
    }
}

// one block per direction; 1024-thread chunked exclusive scan of counts
__global__ void scan_kernel(int n) {
    int dir = blockIdx.x;
    const int* cnt = g_cnt[dir];
    int* off = g_off[dir];
    int* cur = g_cur[dir];
    __shared__ int part[1024];
    int t = threadIdx.x;
    int C = (n + 1023) >> 10;
    int lo = t * C;
    int hi = lo + C; if (hi > n) hi = n; if (lo > n) lo = n;
    int s = 0;
    for (int i = lo; i < hi; i++) s += cnt[i];
    part[t] = s;
    __syncthreads();
    for (int d = 1; d < 1024; d <<= 1) {
        int v = (t >= d) ? part[t - d] : 0;
        __syncthreads();
        part[t] += v;
        __syncthreads();
    }
    int base = (t == 0) ? 0 : part[t - 1];
    for (int i = lo; i < hi; i++) { off[i] = base; cur[i] = base; base += cnt[i]; }
    if (t == 1023) off[n] = part[1023];
}

__global__ void place_kernel(const int* __restrict__ src, const int* __restrict__ dst, int E) {
    int e = blockIdx.x * blockDim.x + threadIdx.x;
    if (e < E) {
        int s = src[e], d = dst[e];
        int p = atomicAdd(&g_cur[0][d], 1); g_adj[0][p] = s;
        int q = atomicAdd(&g_cur[1][s], 1); g_adj[1][q] = d;
    }
}

// ---------------- atomic-free segment sum: z[v] = sum over in-neighbors of m[u] ----
// one warp per node, float4 per lane (128 floats = 1 warp * 4 per lane)
__global__ void gather_kernel(int dir, int n) {
    int w = (blockIdx.x * blockDim.x + threadIdx.x) >> 5;
    int lane = threadIdx.x & 31;
    if (w >= n) return;
    const int* __restrict__ off = g_off[dir];
    const int* __restrict__ adj = g_adj[dir];
    const float4* __restrict__ m4 = (const float4*)g_m;
    float4* __restrict__ z4 = (float4*)g_z;
    int lo = off[w], hi = off[w + 1];
    float4 acc = make_float4(0.f, 0.f, 0.f, 0.f);
    int j = lo;
    for (; j + 2 <= hi; j += 2) {
        int s0 = adj[j], s1 = adj[j + 1];
        float4 v0 = m4[s0 * 32 + lane];
        float4 v1 = m4[s1 * 32 + lane];
        acc.x += v0.x + v1.x; acc.y += v0.y + v1.y;
        acc.z += v0.z + v1.z; acc.w += v0.w + v1.w;
    }
    if (j < hi) {
        int s0 = adj[j];
        float4 v0 = m4[s0 * 32 + lane];
        acc.x += v0.x; acc.y += v0.y; acc.z += v0.z; acc.w += v0.w;
    }
    z4[w * 32 + lane] = acc;
}

// ---------------- fused 2-layer MLP: out = epi( relu(A@W1+b1) @ W2 + b2 ) ------
// MODE 0: plain store (stride 128)            — self_trans
// MODE 1: relu, store (stride 128)            — message MLP
// MODE 2: relu, zero sink, += self, stride128 — update MLP, mid iterations
// MODE 3: like 2, but store to out stride 256 at column offset — last iteration
template <int MODE>
__global__ void __launch_bounds__(256, 1)
mlp_kernel(const float* __restrict__ A,
           const float* __restrict__ W1, const float* __restrict__ B1,
           const float* __restrict__ W2, const float* __restrict__ B2,
           float* __restrict__ out, const float* __restrict__ self_t,
           int sink, int n, int outOfs)
{
    extern __shared__ float smem[];
    float* sW = smem;              // 16384 floats (64KB): W1 then W2
    float* sX = smem + 16384;      // 16384 floats (64KB): A tile, reused as hidden
    float4* sW4 = (float4*)sW;
    float4* sX4 = (float4*)sX;

    int t = threadIdx.x;
    int tx = t & 15, ty = t >> 4;
    int r0 = ty * 8, c0 = tx * 8;
    int rowBase = blockIdx.x * BM;

    // load A tile [BM x 128] row-major, zero-padded past n
    const float4* A4 = (const float4*)A;
    #pragma unroll 4
    for (int f = t; f < 4096; f += 256) {
        int m = f >> 5;
        int gr = rowBase + m;
        sX4[f] = (gr < n) ? __ldg(&A4[gr * 32 + (f & 31)])
                          : make_float4(0.f, 0.f, 0.f, 0.f);
    }
    // load W1 [128 x 128]
    #pragma unroll 4
    for (int f = t; f < 4096; f += 256) sW4[f] = __ldg(&((const float4*)W1)[f]);
    __syncthreads();

    float acc[8][8];
    #pragma unroll
    for (int i = 0; i < 8; i++)
        #pragma unroll
        for (int j = 0; j < 8; j++) acc[i][j] = 0.f;

    // stage 1: hidden = relu(A @ W1 + b1)
    #pragma unroll 4
    for (int k = 0; k < 128; k++) {
        float a[8], w[8];
        #pragma unroll
        for (int i = 0; i < 8; i++) a[i] = sX[(r0 + i) * 128 + k];
        float4 wa = sW4[k * 32 + (c0 >> 2)];
        float4 wb = sW4[k * 32 + (c0 >> 2) + 1];
        w[0] = wa.x; w[1] = wa.y; w[2] = wa.z; w[3] = wa.w;
        w[4] = wb.x; w[5] = wb.y; w[6] = wb.z; w[7] = wb.w;
        #pragma unroll
        for (int i = 0; i < 8; i++)
            #pragma unroll
            for (int j = 0; j < 8; j++)
                acc[i][j] = fmaf(a[i], w[j], acc[i][j]);
    }
    __syncthreads();  // all stage-1 reads of sX/sW done

    {
        float rb[8];
        #pragma unroll
        for (int j = 0; j < 8; j++) rb[j] = __ldg(&B1[c0 + j]);
        #pragma unroll
        for (int i = 0; i < 8; i++) {
            float4 v0, v1;
            v0.x = fmaxf(acc[i][0] + rb[0], 0.f);
            v0.y = fmaxf(acc[i][1] + rb[1], 0.f);
            v0.z = fmaxf(acc[i][2] + rb[2], 0.f);
            v0.w = fmaxf(acc[i][3] + rb[3], 0.f);
            v1.x = fmaxf(acc[i][4] + rb[4], 0.f);
            v1.y = fmaxf(acc[i][5] + rb[5], 0.f);
            v1.z = fmaxf(acc[i][6] + rb[6], 0.f);
            v1.w = fmaxf(acc[i][7] + rb[7], 0.f);
            sX4[((r0 + i) * 128 + c0) >> 2] = v0;
            sX4[((r0 + i) * 128 + c0 + 4) >> 2] = v1;
        }
    }
    // overwrite sW with W2 (stage-1 reads already fenced by the sync above)
    #pragma unroll 4
    for (int f = t; f < 4096; f += 256) sW4[f] = __ldg(&((const float4*)W2)[f]);
    __syncthreads();

    #pragma unroll
    for (int i = 0; i < 8; i++)
        #pragma unroll
        for (int j = 0; j < 8; j++) acc[i][j] = 0.f;

    // stage 2: out = hidden @ W2 + b2
    #pragma unroll 4
    for (int k = 0; k < 128; k++) {
        float a[8], w[8];
        #pragma unroll
        for (int i = 0; i < 8; i++) a[i] = sX[(r0 + i) * 128 + k];
        float4 wa = sW4[k * 32 + (c0 >> 2)];
        float4 wb = sW4[k * 32 + (c0 >> 2) + 1];
        w[0] = wa.x; w[1] = wa.y; w[2] = wa.z; w[3] = wa.w;
        w[4] = wb.x; w[5] = wb.y; w[6] = wb.z; w[7] = wb.w;
        #pragma unroll
        for (int i = 0; i < 8; i++)
            #pragma unroll
            for (int j = 0; j < 8; j++)
                acc[i][j] = fmaf(a[i], w[j], acc[i][j]);
    }

    // epilogue
    float rb[8];
    #pragma unroll
    for (int j = 0; j < 8; j++) rb[j] = __ldg(&B2[c0 + j]);
    #pragma unroll
    for (int i = 0; i < 8; i++) {
        int gr = rowBase + r0 + i;
        if (gr >= n) continue;
        #pragma unroll
        for (int j = 0; j < 8; j++) {
            float v = acc[i][j] + rb[j];
            if (MODE >= 1) v = fmaxf(v, 0.f);
            if (MODE >= 2) {
                if (gr == sink) v = 0.f;
                v += self_t[gr * 128 + c0 + j];
            }
            if (MODE == 3) out[gr * 256 + outOfs + c0 + j] = v;
            else           out[gr * 128 + c0 + j] = v;
        }
    }
}

// ---------------- launch ----------------
extern "C" void kernel_launch(void* const* d_in, const int* in_sizes, int n_in,
                              void* d_out, int out_size)
{
    const float* feat = (const float*)d_in[0];
    const int* src = (const int*)d_in[1];
    const int* dst = (const int*)d_in[2];
    const float* P[20];
    for (int i = 0; i < 20; i++) P[i] = (const float*)d_in[3 + i];
    // P: [0..3]=nt, [4..7]=fp, [8..11]=fu, [12..15]=bp, [16..19]=bu (w1,b1,w2,b2)
    float* out = (float*)d_out;

    int N = in_sizes[0] / DD;
    int E = in_sizes[1];

    const size_t SMEM = 32768 * sizeof(float);  // 128KB
    cudaFuncSetAttribute(mlp_kernel<0>, cudaFuncAttributeMaxDynamicSharedMemorySize, (int)SMEM);
    cudaFuncSetAttribute(mlp_kernel<1>, cudaFuncAttributeMaxDynamicSharedMemorySize, (int)SMEM);
    cudaFuncSetAttribute(mlp_kernel<2>, cudaFuncAttributeMaxDynamicSharedMemorySize, (int)SMEM);
    cudaFuncSetAttribute(mlp_kernel<3>, cudaFuncAttributeMaxDynamicSharedMemorySize, (int)SMEM);

    float *p_self, *p_y, *p_m, *p_z;
    cudaGetSymbolAddress((void**)&p_self, g_self);
    cudaGetSymbolAddress((void**)&p_y, g_y);
    cudaGetSymbolAddress((void**)&p_m, g_m);
    cudaGetSymbolAddress((void**)&p_z, g_z);

    int gb = (N + BM - 1) / BM;
    int eb = (E + 255) / 256;
    int nb = (N + 255) / 256;
    int wb = (N * 32 + 255) / 256;

    // CSR for both directions
    zero_cnt_kernel<<<nb, 256>>>(N);
    hist_kernel<<<eb, 256>>>(src, dst, E);
    scan_kernel<<<2, 1024>>>(N);
    place_kernel<<<eb, 256>>>(src, dst, E);

    // self_trans = FNN(feat, nt)  (no outer relu)
    mlp_kernel<0><<<gb, 256, SMEM>>>(feat, P[0], P[1], P[2], P[3],
                                     p_self, nullptr, -1, N, 0);

    for (int dir = 0; dir < 2; dir++) {
        const float* mw = (dir == 0) ? P[4] : P[12];   // fp / bp  (w1,b1,w2,b2)
        const float* uw = (dir == 0) ? P[8] : P[16];   // fu / bu
        const float* mW1 = mw, *mB1 = mw; // placeholder, real assignment below
        (void)mW1; (void)mB1;
        const float *MW1, *MB1, *MW2, *MB2, *UW1, *UB1, *UW2, *UB2;
        if (dir == 0) { MW1 = P[4];  MB1 = P[5];  MW2 = P[6];  MB2 = P[7];
                        UW1 = P[8];  UB1 = P[9];  UW2 = P[10]; UB2 = P[11]; }
        else          { MW1 = P[12]; MB1 = P[13]; MW2 = P[14]; MB2 = P[15];
                        UW1 = P[16]; UB1 = P[17]; UW2 = P[18]; UB2 = P[19]; }
        (void)mw; (void)uw;
        int sink = (dir == 0) ? (N - 1) : 0;
        int ofs = (dir == 0) ? 0 : 128;

        const float* yin = p_self;
        for (int k = 0; k < 3; k++) {
            // per-node message MLP: m = relu(FNN(y))   [FNN(y[src]) == FNN(y)[src]]
            mlp_kernel<1><<<gb, 256, SMEM>>>(yin, MW1, MB1, MW2, MB2,
                                             p_m, nullptr, -1, N, 0);
            // z[v] = sum_{u in in(v)} m[u]
            gather_kernel<<<wb, 256>>>(dir, N);
            if (k < 2) {
                mlp_kernel<2><<<gb, 256, SMEM>>>(p_z, UW1, UB1, UW2, UB2,
                                                 p_y, p_self, sink, N, 0);
                yin = p_y;
            } else {
                mlp_kernel<3><<<gb, 256, SMEM>>>(p_z, UW1, UB1, UW2, UB2,
                                                 out, p_self, sink, N, ofs);
            }
        }
    }
}

// round 3
// speedup vs baseline: 2.2586x; 2.2586x over previous
#include <cuda_runtime.h>
#include <cuda_bf16.h>
#include <cstdint>

#define NN 50000
#define EE 800000
#define DD 128
#define BM 64
#define PB 272   // smem row pitch in bytes (136 bf16)

// ---------------- device scratch (static, allocation-free) ----------------
__device__ float g_self[NN * DD];
__device__ float g_y[NN * DD];
__device__ float g_m[NN * DD];
__device__ float g_z[NN * DD];
__device__ int g_cnt[2][NN];
__device__ int g_off[2][NN + 1];
__device__ int g_cur[2][NN];
__device__ int g_adj[2][EE];
// plain row-major bf16 hi/lo weight planes: [matrix 0..9][hi/lo][128*128], W[k][n]
__device__ __nv_bfloat16 g_wimg[10][2][DD * DD];

// ---------------- helpers ----------------
__device__ __forceinline__ uint32_t smem_u32(const void* p) {
    uint32_t a;
    asm("{ .reg .u64 t; cvta.to.shared.u64 t, %1; cvt.u32.u64 %0, t; }" : "=r"(a) : "l"(p));
    return a;
}
__device__ __forceinline__ void ldm_x4(uint32_t* r, uint32_t addr) {
    asm volatile("ldmatrix.sync.aligned.m8n8.x4.shared.b16 {%0,%1,%2,%3}, [%4];"
                 : "=r"(r[0]), "=r"(r[1]), "=r"(r[2]), "=r"(r[3]) : "r"(addr));
}
__device__ __forceinline__ void ldm_x4t(uint32_t* r, uint32_t addr) {
    asm volatile("ldmatrix.sync.aligned.m8n8.x4.trans.shared.b16 {%0,%1,%2,%3}, [%4];"
                 : "=r"(r[0]), "=r"(r[1]), "=r"(r[2]), "=r"(r[3]) : "r"(addr));
}
__device__ __forceinline__ void mma16816(float* c, const uint32_t* a, uint32_t b0, uint32_t b1) {
    asm volatile("mma.sync.aligned.m16n8k16.row.col.f32.bf16.bf16.f32 "
                 "{%0,%1,%2,%3}, {%4,%5,%6,%7}, {%8,%9}, {%0,%1,%2,%3};"
                 : "+f"(c[0]), "+f"(c[1]), "+f"(c[2]), "+f"(c[3])
                 : "r"(a[0]), "r"(a[1]), "r"(a[2]), "r"(a[3]), "r"(b0), "r"(b1));
}
__device__ __forceinline__ uint32_t packbf2(float x, float y) {
    __nv_bfloat162 h = __floats2bfloat162_rn(x, y);
    return *(uint32_t*)&h;
}

// ---------------- CSR construction ----------------
__global__ void zero_cnt_kernel(int n) {
    int i = blockIdx.x * blockDim.x + threadIdx.x;
    if (i < n) { g_cnt[0][i] = 0; g_cnt[1][i] = 0; }
}
__global__ void hist_kernel(const int* __restrict__ src, const int* __restrict__ dst, int E) {
    int e = blockIdx.x * blockDim.x + threadIdx.x;
    if (e < E) {
        atomicAdd(&g_cnt[0][dst[e]], 1);
        atomicAdd(&g_cnt[1][src[e]], 1);
    }
}
__global__ void scan_kernel(int n) {
    int dir = blockIdx.x;
    const int* cnt = g_cnt[dir];
    int* off = g_off[dir];
    int* cur = g_cur[dir];
    __shared__ int part[1024];
    int t = threadIdx.x;
    int C = (n + 1023) >> 10;
    int lo = t * C;
    int hi = lo + C; if (hi > n) hi = n; if (lo > n) lo = n;
    int s = 0;
    for (int i = lo; i < hi; i++) s += cnt[i];
    part[t] = s;
    __syncthreads();
    for (int d = 1; d < 1024; d <<= 1) {
        int v = (t >= d) ? part[t - d] : 0;
        __syncthreads();
        part[t] += v;
        __syncthreads();
    }
    int base = (t == 0) ? 0 : part[t - 1];
    for (int i = lo; i < hi; i++) { off[i] = base; cur[i] = base; base += cnt[i]; }
    if (t == 1023) off[n] = part[1023];
}
__global__ void place_kernel(const int* __restrict__ src, const int* __restrict__ dst, int E) {
    int e = blockIdx.x * blockDim.x + threadIdx.x;
    if (e < E) {
        int s = src[e], d = dst[e];
        int p = atomicAdd(&g_cur[0][d], 1); g_adj[0][p] = s;
        int q = atomicAdd(&g_cur[1][s], 1); g_adj[1][q] = d;
    }
}

// ---------------- atomic-free segment sum ----------------
__global__ void gather_kernel(int dir, int n) {
    int w = (blockIdx.x * blockDim.x + threadIdx.x) >> 5;
    int lane = threadIdx.x & 31;
    if (w >= n) return;
    const int* __restrict__ off = g_off[dir];
    const int* __restrict__ adj = g_adj[dir];
    const float4* __restrict__ m4 = (const float4*)g_m;
    float4* __restrict__ z4 = (float4*)g_z;
    int lo = off[w], hi = off[w + 1];
    float4 acc = make_float4(0.f, 0.f, 0.f, 0.f);
    int j = lo;
    for (; j + 2 <= hi; j += 2) {
        int s0 = adj[j], s1 = adj[j + 1];
        float4 v0 = m4[s0 * 32 + lane];
        float4 v1 = m4[s1 * 32 + lane];
        acc.x += v0.x + v1.x; acc.y += v0.y + v1.y;
        acc.z += v0.z + v1.z; acc.w += v0.w + v1.w;
    }
    if (j < hi) {
        int s0 = adj[j];
        float4 v0 = m4[s0 * 32 + lane];
        acc.x += v0.x; acc.y += v0.y; acc.z += v0.z; acc.w += v0.w;
    }
    z4[w * 32 + lane] = acc;
}

// ---------------- weight preprocessing: fp32 W[k][n] -> bf16 hi/lo planes ----
struct WPtrs { const float* p[10]; };
__global__ void prep_w_kernel(WPtrs wp) {
    int e = blockIdx.x * blockDim.x + threadIdx.x;
    if (e >= 10 * DD * DD) return;
    int m = e / (DD * DD);
    int idx = e % (DD * DD);
    float w = wp.p[m][idx];
    __nv_bfloat16 hi = __float2bfloat16(w);
    __nv_bfloat16 lo = __float2bfloat16(w - __bfloat162float(hi));
    g_wimg[m][0][idx] = hi;
    g_wimg[m][1][idx] = lo;
}

// ---------------- HMMA fused 2-layer MLP ----------------
// smem: A hi/lo planes (64 rows x PB), W hi/lo planes (128 rows x PB)
#define SM_AH 0
#define SM_AL 17408
#define SM_WH 34816
#define SM_WL 69632
#define SMEM_BYTES 104448

// inner GEMM: acc += A(64x128, hi/lo split) @ W(128x128, hi/lo split)
__device__ __forceinline__ void gemm_tile(uint32_t sAh, uint32_t sAl,
                                          uint32_t sWh, uint32_t sWl,
                                          int warp_m, int warp_n, int lane,
                                          float acc[2][4][4])
{
    int l7 = lane & 7;
    int j = lane >> 3;
    // A frag lane address: row = warp_m*32 + mt*16 + (j&1)*8 + l7, colbyte = (j>>1)*16 + ks*32
    uint32_t aRow = (uint32_t)(warp_m * 32 + (j & 1) * 8 + l7);
    uint32_t aBase = aRow * PB + (uint32_t)((j >> 1) * 16);
    // B frag lane address: row = ks*16 + (j&1)*8 + l7, colbyte = (warp_n*32 + (j>>1)*8)*2 + pair*32
    uint32_t bRow = (uint32_t)((j & 1) * 8 + l7);
    uint32_t bBase = bRow * PB + (uint32_t)((warp_n * 32 + (j >> 1) * 8) * 2);

    #pragma unroll
    for (int ks = 0; ks < 8; ks++) {
        uint32_t ah[2][4], al[2][4], bh[2][4], bl[2][4];
        uint32_t aOff = aBase + (uint32_t)(ks * 32);
        uint32_t bOff = bBase + (uint32_t)(ks * 16) * PB;
        #pragma unroll
        for (int mt = 0; mt < 2; mt++) {
            ldm_x4(ah[mt], sAh + aOff + (uint32_t)(mt * 16) * PB);
            ldm_x4(al[mt], sAl + aOff + (uint32_t)(mt * 16) * PB);
        }
        #pragma unroll
        for (int p = 0; p < 2; p++) {
            ldm_x4t(bh[p], sWh + bOff + (uint32_t)(p * 32));
            ldm_x4t(bl[p], sWl + bOff + (uint32_t)(p * 32));
        }
        #pragma unroll
        for (int mt = 0; mt < 2; mt++)
            #pragma unroll
            for (int p = 0; p < 2; p++)
                #pragma unroll
                for (int h = 0; h < 2; h++) {
                    int nt = p * 2 + h;
                    mma16816(acc[mt][nt], ah[mt], bh[p][2 * h], bh[p][2 * h + 1]);
                    mma16816(acc[mt][nt], ah[mt], bl[p][2 * h], bl[p][2 * h + 1]);
                    mma16816(acc[mt][nt], al[mt], bh[p][2 * h], bh[p][2 * h + 1]);
                }
    }
}

__device__ __forceinline__ void copy_w(char* smem, int off, const __nv_bfloat16* w, int t) {
    const float4* s = (const float4*)w;
    #pragma unroll
    for (int f = t; f < 2048; f += 256) {
        int row = f >> 4, q = f & 15;
        *(float4*)(smem + off + row * PB + q * 16) = __ldg(&s[f]);
    }
}

// MODE 0: plain store (stride 128)            — self_trans
// MODE 1: relu, store (stride 128)            — message MLP
// MODE 2: relu, zero sink, += self, stride128 — update MLP, mid iterations
// MODE 3: like 2, store to out stride 256 at column offset — last iteration
template <int MODE>
__global__ void __launch_bounds__(256, 2)
mma_mlp(const float* __restrict__ A,
        const __nv_bfloat16* __restrict__ w1h, const __nv_bfloat16* __restrict__ w1l,
        const __nv_bfloat16* __restrict__ w2h, const __nv_bfloat16* __restrict__ w2l,
        const float* __restrict__ B1, const float* __restrict__ B2,
        float* __restrict__ out, const float* __restrict__ self_t,
        int sink, int n, int outOfs)
{
    extern __shared__ __align__(16) char smem[];
    uint32_t sb = smem_u32(smem);
    int t = threadIdx.x;
    int wid = t >> 5, lane = t & 31;
    int warp_m = wid & 1, warp_n = wid >> 1;
    int rowBase = blockIdx.x * BM;

    // load A tile [64 x 128] fp32 -> bf16 hi/lo planes
    {
        const float4* A4 = (const float4*)A;
        #pragma unroll
        for (int f = t; f < 2048; f += 256) {
            int m = f >> 5, kq = f & 31;
            int gr = rowBase + m;
            float4 a = (gr < n) ? __ldg(&A4[gr * 32 + kq])
                                : make_float4(0.f, 0.f, 0.f, 0.f);
            __nv_bfloat16 hx = __float2bfloat16(a.x), hy = __float2bfloat16(a.y);
            __nv_bfloat16 hz = __float2bfloat16(a.z), hw = __float2bfloat16(a.w);
            uint2 hiu, lou;
            {
                __nv_bfloat162 p0; p0.x = hx; p0.y = hy;
                __nv_bfloat162 p1; p1.x = hz; p1.y = hw;
                hiu.x = *(uint32_t*)&p0; hiu.y = *(uint32_t*)&p1;
            }
            lou.x = packbf2(a.x - __bfloat162float(hx), a.y - __bfloat162float(hy));
            lou.y = packbf2(a.z - __bfloat162float(hz), a.w - __bfloat162float(hw));
            *(uint2*)(smem + SM_AH + m * PB + kq * 8) = hiu;
            *(uint2*)(smem + SM_AL + m * PB + kq * 8) = lou;
        }
    }
    copy_w(smem, SM_WH, w1h, t);
    copy_w(smem, SM_WL, w1l, t);
    __syncthreads();

    float acc[2][4][4];
    #pragma unroll
    for (int i = 0; i < 2; i++)
        #pragma unroll
        for (int j = 0; j < 4; j++)
            #pragma unroll
            for (int k = 0; k < 4; k++) acc[i][j][k] = 0.f;

    gemm_tile(sb + SM_AH, sb + SM_AL, sb + SM_WH, sb + SM_WL, warp_m, warp_n, lane, acc);
    __syncthreads();   // GEMM1 reads of sA/sW done

    // epilogue 1: hidden = relu(acc + b1) -> bf16 hi/lo back into A planes
    {
        int l4 = lane >> 2, q = lane & 3;
        #pragma unroll
        for (int mt = 0; mt < 2; mt++)
            #pragma unroll
            for (int nt = 0; nt < 4; nt++) {
                int row = warp_m * 32 + mt * 16 + l4;
                int col = warp_n * 32 + nt * 8 + q * 2;
                float2 b = __ldg((const float2*)&B1[col]);
                #pragma unroll
                for (int h = 0; h < 2; h++) {   // h=0: rows 0-7, h=1: rows 8-15
                    float v0 = fmaxf(acc[mt][nt][2 * h + 0] + b.x, 0.f);
                    float v1 = fmaxf(acc[mt][nt][2 * h + 1] + b.y, 0.f);
                    __nv_bfloat16 h0 = __float2bfloat16(v0);
                    __nv_bfloat16 h1 = __float2bfloat16(v1);
                    uint32_t hu = ((uint32_t)*(uint16_t*)&h1 << 16) | *(uint16_t*)&h0;
                    uint32_t lu = packbf2(v0 - __bfloat162float(h0), v1 - __bfloat162float(h1));
                    int r = row + h * 8;
                    *(uint32_t*)(smem + SM_AH + r * PB + col * 2) = hu;
                    *(uint32_t*)(smem + SM_AL + r * PB + col * 2) = lu;
                }
            }
    }
    // overwrite W planes with W2 (W1 reads fenced by sync above)
    copy_w(smem, SM_WH, w2h, t);
    copy_w(smem, SM_WL, w2l, t);
    __syncthreads();

    #pragma unroll
    for (int i = 0; i < 2; i++)
        #pragma unroll
        for (int j = 0; j < 4; j++)
            #pragma unroll
            for (int k = 0; k < 4; k++) acc[i][j][k] = 0.f;

    gemm_tile(sb + SM_AH, sb + SM_AL, sb + SM_WH, sb + SM_WL, warp_m, warp_n, lane, acc);

    // epilogue 2: out = epi(acc + b2)
    {
        int l4 = lane >> 2, q = lane & 3;
        int stride = (MODE == 3) ? 256 : 128;
        #pragma unroll
        for (int mt = 0; mt < 2; mt++)
            #pragma unroll
            for (int nt = 0; nt < 4; nt++) {
                int col = warp_n * 32 + nt * 8 + q * 2;
                float2 b = __ldg((const float2*)&B2[col]);
                #pragma unroll
                for (int h = 0; h < 2; h++) {
                    int gr = rowBase + warp_m * 32 + mt * 16 + l4 + h * 8;
                    if (gr >= n) continue;
                    float2 v;
                    v.x = acc[mt][nt][2 * h + 0] + b.x;
                    v.y = acc[mt][nt][2 * h + 1] + b.y;
                    if (MODE >= 1) { v.x = fmaxf(v.x, 0.f); v.y = fmaxf(v.y, 0.f); }
                    if (MODE >= 2) {
                        if (gr == sink) { v.x = 0.f; v.y = 0.f; }
                        float2 s2 = __ldg((const float2*)&self_t[gr * 128 + col]);
                        v.x += s2.x; v.y += s2.y;
                    }
                    *(float2*)&out[gr * stride + outOfs + col] = v;
                }
            }
    }
}

// ---------------- launch ----------------
extern "C" void kernel_launch(void* const* d_in, const int* in_sizes, int n_in,
                              void* d_out, int out_size)
{
    const float* feat = (const float*)d_in[0];
    const int* src = (const int*)d_in[1];
    const int* dst = (const int*)d_in[2];
    const float* P[20];
    for (int i = 0; i < 20; i++) P[i] = (const float*)d_in[3 + i];
    float* out = (float*)d_out;

    int N = in_sizes[0] / DD;
    int E = in_sizes[1];

    cudaFuncSetAttribute(mma_mlp<0>, cudaFuncAttributeMaxDynamicSharedMemorySize, SMEM_BYTES);
    cudaFuncSetAttribute(mma_mlp<1>, cudaFuncAttributeMaxDynamicSharedMemorySize, SMEM_BYTES);
    cudaFuncSetAttribute(mma_mlp<2>, cudaFuncAttributeMaxDynamicSharedMemorySize, SMEM_BYTES);
    cudaFuncSetAttribute(mma_mlp<3>, cudaFuncAttributeMaxDynamicSharedMemorySize, SMEM_BYTES);

    float *p_self, *p_y, *p_m, *p_z;
    cudaGetSymbolAddress((void**)&p_self, g_self);
    cudaGetSymbolAddress((void**)&p_y, g_y);
    cudaGetSymbolAddress((void**)&p_m, g_m);
    cudaGetSymbolAddress((void**)&p_z, g_z);
    __nv_bfloat16* wbase;
    cudaGetSymbolAddress((void**)&wbase, g_wimg);
    auto wimg = [&](int m, int p) -> const __nv_bfloat16* {
        return wbase + (size_t)(m * 2 + p) * DD * DD;
    };

    int gb = (N + BM - 1) / BM;
    int eb = (E + 255) / 256;
    int nb = (N + 255) / 256;
    int wb = (N * 32 + 255) / 256;

    // CSR for both directions
    zero_cnt_kernel<<<nb, 256>>>(N);
    hist_kernel<<<eb, 256>>>(src, dst, E);
    scan_kernel<<<2, 1024>>>(N);
    place_kernel<<<eb, 256>>>(src, dst, E);

    // weight hi/lo planes: {nt1,nt2,fp1,fp2,fu1,fu2,bp1,bp2,bu1,bu2}
    WPtrs wp;
    wp.p[0] = P[0];  wp.p[1] = P[2];
    wp.p[2] = P[4];  wp.p[3] = P[6];
    wp.p[4] = P[8];  wp.p[5] = P[10];
    wp.p[6] = P[12]; wp.p[7] = P[14];
    wp.p[8] = P[16]; wp.p[9] = P[18];
    prep_w_kernel<<<(10 * DD * DD + 255) / 256, 256>>>(wp);

    // self_trans = FNN(feat, nt)
    mma_mlp<0><<<gb, 256, SMEM_BYTES>>>(feat, wimg(0, 0), wimg(0, 1), wimg(1, 0), wimg(1, 1),
                                        P[1], P[3], p_self, nullptr, -1, N, 0);

    for (int dir = 0; dir < 2; dir++) {
        int mi1, mi2, ui1, ui2;
        const float *MB1, *MB2, *UB1, *UB2;
        if (dir == 0) { mi1 = 2; mi2 = 3; ui1 = 4; ui2 = 5;
                        MB1 = P[5];  MB2 = P[7];  UB1 = P[9];  UB2 = P[11]; }
        else          { mi1 = 6; mi2 = 7; ui1 = 8; ui2 = 9;
                        MB1 = P[13]; MB2 = P[15]; UB1 = P[17]; UB2 = P[19]; }
        int sink = (dir == 0) ? (N - 1) : 0;
        int ofs = (dir == 0) ? 0 : 128;

        const float* yin = p_self;
        for (int k = 0; k < 3; k++) {
            // per-node message MLP: m = relu(FNN(y))  [FNN(y[src]) == FNN(y)[src]]
            mma_mlp<1><<<gb, 256, SMEM_BYTES>>>(yin, wimg(mi1, 0), wimg(mi1, 1),
                                                wimg(mi2, 0), wimg(mi2, 1),
                                                MB1, MB2, p_m, nullptr, -1, N, 0);
            // z[v] = sum_{u in in(v)} m[u]
            gather_kernel<<<wb, 256>>>(dir, N);
            if (k < 2) {
                mma_mlp<2><<<gb, 256, SMEM_BYTES>>>(p_z, wimg(ui1, 0), wimg(ui1, 1),
                                                    wimg(ui2, 0), wimg(ui2, 1),
                                                    UB1, UB2, p_y, p_self, sink, N, 0);
                yin = p_y;
            } else {
                mma_mlp<3><<<gb, 256, SMEM_BYTES>>>(p_z, wimg(ui1, 0), wimg(ui1, 1),
                                                    wimg(ui2, 0), wimg(ui2, 1),
                                                    UB1, UB2, out, p_self, sink, N, ofs);
            }
        }
    }
}

// round 5
// speedup vs baseline: 2.4146x; 1.0691x over previous
#include <cuda_runtime.h>
#include <cuda_fp16.h>
#include <cstdint>

#define NN 50000
#define EE 800000
#define DD 128
#define BM 64
#define PB 272   // smem row pitch in bytes (136 fp16)

#define ACT_S 0.015625f   // 2^-6: activation scale into fp16
#define ACT_I 64.0f       // inverse

// ---------------- device scratch (static, allocation-free) ----------------
__device__ float g_self[NN * DD];
__device__ float g_y[NN * DD];
__device__ float g_m[NN * DD];
__device__ int g_cnt[2][NN];
__device__ int g_off[2][NN + 1];
__device__ int g_cur[2][NN];
__device__ int g_adj[2][EE];
// row-major fp16 hi/lo weight planes: [matrix 0..9][hi/lo][128*128], W[k][n]
__device__ __half g_wimg[10][2][DD * DD];

// ---------------- helpers ----------------
__device__ __forceinline__ uint32_t smem_u32(const void* p) {
    uint32_t a;
    asm("{ .reg .u64 t; cvta.to.shared.u64 t, %1; cvt.u32.u64 %0, t; }" : "=r"(a) : "l"(p));
    return a;
}
__device__ __forceinline__ void ldm_x4(uint32_t* r, uint32_t addr) {
    asm volatile("ldmatrix.sync.aligned.m8n8.x4.shared.b16 {%0,%1,%2,%3}, [%4];"
                 : "=r"(r[0]), "=r"(r[1]), "=r"(r[2]), "=r"(r[3]) : "r"(addr));
}
__device__ __forceinline__ void ldm_x4t(uint32_t* r, uint32_t addr) {
    asm volatile("ldmatrix.sync.aligned.m8n8.x4.trans.shared.b16 {%0,%1,%2,%3}, [%4];"
                 : "=r"(r[0]), "=r"(r[1]), "=r"(r[2]), "=r"(r[3]) : "r"(addr));
}
__device__ __forceinline__ void mma16816(float* c, const uint32_t* a, uint32_t b0, uint32_t b1) {
    asm volatile("mma.sync.aligned.m16n8k16.row.col.f32.f16.f16.f32 "
                 "{%0,%1,%2,%3}, {%4,%5,%6,%7}, {%8,%9}, {%0,%1,%2,%3};"
                 : "+f"(c[0]), "+f"(c[1]), "+f"(c[2]), "+f"(c[3])
                 : "r"(a[0]), "r"(a[1]), "r"(a[2]), "r"(a[3]), "r"(b0), "r"(b1));
}
__device__ __forceinline__ uint32_t packh2(float x, float y) {
    __half2 h = __floats2half2_rn(x, y);
    return *(uint32_t*)&h;
}

// ---------------- CSR construction ----------------
__global__ void zero_cnt_kernel(int n) {
    int i = blockIdx.x * blockDim.x + threadIdx.x;
    if (i < n) { g_cnt[0][i] = 0; g_cnt[1][i] = 0; }
}
__global__ void hist_kernel(const int* __restrict__ src, const int* __restrict__ dst, int E) {
    int e = blockIdx.x * blockDim.x + threadIdx.x;
    if (e < E) {
        atomicAdd(&g_cnt[0][dst[e]], 1);
        atomicAdd(&g_cnt[1][src[e]], 1);
    }
}
__global__ void scan_kernel(int n) {
    int dir = blockIdx.x;
    const int* cnt = g_cnt[dir];
    int* off = g_off[dir];
    int* cur = g_cur[dir];
    __shared__ int part[1024];
    int t = threadIdx.x;
    int C = (n + 1023) >> 10;
    int lo = t * C;
    int hi = lo + C; if (hi > n) hi = n; if (lo > n) lo = n;
    int s = 0;
    for (int i = lo; i < hi; i++) s += cnt[i];
    part[t] = s;
    __syncthreads();
    for (int d = 1; d < 1024; d <<= 1) {
        int v = (t >= d) ? part[t - d] : 0;
        __syncthreads();
        part[t] += v;
        __syncthreads();
    }
    int base = (t == 0) ? 0 : part[t - 1];
    for (int i = lo; i < hi; i++) { off[i] = base; cur[i] = base; base += cnt[i]; }
    if (t == 1023) off[n] = part[1023];
}
__global__ void place_kernel(const int* __restrict__ src, const int* __restrict__ dst, int E) {
    int e = blockIdx.x * blockDim.x + threadIdx.x;
    if (e < E) {
        int s = src[e], d = dst[e];
        int p = atomicAdd(&g_cur[0][d], 1); g_adj[0][p] = s;
        int q = atomicAdd(&g_cur[1][s], 1); g_adj[1][q] = d;
    }
}

// ---------------- weight preprocessing: fp32 W[k][n] -> fp16 hi/lo planes ----
struct WPtrs { const float* p[10]; };
__global__ void prep_w_kernel(WPtrs wp) {
    int e = blockIdx.x * blockDim.x + threadIdx.x;
    if (e >= 10 * DD * DD) return;
    int m = e / (DD * DD);
    int idx = e % (DD * DD);
    float w = wp.p[m][idx];
    __half hi = __float2half_rn(w);
    __half lo = __float2half_rn(w - __half2float(hi));
    g_wimg[m][0][idx] = hi;
    g_wimg[m][1][idx] = lo;
}

// ---------------- fused MLP (+ optional CSR gather front-end) ----------------
// smem: A plane (64 x PB fp16), W hi/lo planes (128 x PB fp16 each)
#define SM_A  0
#define SM_WH 17408
#define SM_WL 52224
#define SMEM_BYTES 87040

// inner GEMM: acc += A(64x128 fp16) @ (Wh + Wl)(128x128 fp16 split)
__device__ __forceinline__ void gemm_tile(uint32_t sA, uint32_t sWh, uint32_t sWl,
                                          int warp_m, int warp_n, int lane,
                                          float acc[2][4][4])
{
    int l7 = lane & 7;
    int j = lane >> 3;
    uint32_t aRow = (uint32_t)(warp_m * 32 + (j & 1) * 8 + l7);
    uint32_t aBase = aRow * PB + (uint32_t)((j >> 1) * 16);
    uint32_t bRow = (uint32_t)((j & 1) * 8 + l7);
    uint32_t bBase = bRow * PB + (uint32_t)((warp_n * 32 + (j >> 1) * 8) * 2);

    #pragma unroll
    for (int ks = 0; ks < 8; ks++) {
        uint32_t ah[2][4], bh[2][4], bl[2][4];
        uint32_t aOff = aBase + (uint32_t)(ks * 32);
        uint32_t bOff = bBase + (uint32_t)(ks * 16) * PB;
        #pragma unroll
        for (int mt = 0; mt < 2; mt++)
            ldm_x4(ah[mt], sA + aOff + (uint32_t)(mt * 16) * PB);
        #pragma unroll
        for (int p = 0; p < 2; p++) {
            ldm_x4t(bh[p], sWh + bOff + (uint32_t)(p * 32));
            ldm_x4t(bl[p], sWl + bOff + (uint32_t)(p * 32));
        }
        #pragma unroll
        for (int mt = 0; mt < 2; mt++)
            #pragma unroll
            for (int p = 0; p < 2; p++)
                #pragma unroll
                for (int h = 0; h < 2; h++) {
                    int nt = p * 2 + h;
                    mma16816(acc[mt][nt], ah[mt], bh[p][2 * h], bh[p][2 * h + 1]);
                    mma16816(acc[mt][nt], ah[mt], bl[p][2 * h], bl[p][2 * h + 1]);
                }
    }
}

// copy one 128x128 fp16 plane (256B/row = 16 float4 chunks, 2048 total)
__device__ __forceinline__ void copy_w(char* smem, int off, const __half* w, int t) {
    const float4* s = (const float4*)w;
    #pragma unroll
    for (int f = t; f < 2048; f += 256) {
        int row = f >> 4, q = f & 15;
        *(float4*)(smem + off + row * PB + q * 16) = __ldg(&s[f]);
    }
}

// MODE 0: A from gmem, plain store (stride 128)          — self_trans
// MODE 1: A from gmem, relu, store (stride 128)          — message MLP
// MODE 2: A = CSR-gathered sum of g_m rows; relu, zero sink, += self, store 128
// MODE 3: like 2, store to out stride 256 at column offset — last iteration
template <int MODE>
__global__ void __launch_bounds__(256, 2)
mma_mlp(const float* __restrict__ A,
        const __half* __restrict__ w1h, const __half* __restrict__ w1l,
        const __half* __restrict__ w2h, const __half* __restrict__ w2l,
        const float* __restrict__ B1, const float* __restrict__ B2,
        float* __restrict__ out, const float* __restrict__ self_t,
        int sink, int n, int outOfs, int dir)
{
    extern __shared__ __align__(16) char smem[];
    uint32_t sb = smem_u32(smem);
    int t = threadIdx.x;
    int wid = t >> 5, lane = t & 31;
    int warp_m = wid & 1, warp_n = wid >> 1;
    int rowBase = blockIdx.x * BM;

    if (MODE <= 1) {
        // load A tile [64 x 128] fp32 -> single fp16 plane (scaled by ACT_S)
        const float4* A4 = (const float4*)A;
        #pragma unroll
        for (int f = t; f < 2048; f += 256) {
            int m = f >> 5, kq = f & 31;
            int gr = rowBase + m;
            float4 a = (gr < n) ? __ldg(&A4[gr * 32 + kq])
                                : make_float4(0.f, 0.f, 0.f, 0.f);
            uint2 u;
            u.x = packh2(a.x * ACT_S, a.y * ACT_S);
            u.y = packh2(a.z * ACT_S, a.w * ACT_S);
            *(uint2*)(smem + SM_A + m * PB + kq * 8) = u;
        }
    } else {
        // fused gather: each warp builds 8 rows of A = segment-sum of g_m rows
        const int* __restrict__ off = g_off[dir];
        const int* __restrict__ adj = g_adj[dir];
        const float4* __restrict__ m4 = (const float4*)g_m;
        #pragma unroll
        for (int r = 0; r < 8; r++) {
            int m = wid * 8 + r;
            int gr = rowBase + m;
            float4 acc = make_float4(0.f, 0.f, 0.f, 0.f);
            if (gr < n) {
                int lo = off[gr], hi = off[gr + 1];
                int j = lo;
                for (; j + 2 <= hi; j += 2) {
                    int s0 = adj[j], s1 = adj[j + 1];
                    float4 v0 = m4[s0 * 32 + lane];
                    float4 v1 = m4[s1 * 32 + lane];
                    acc.x += v0.x + v1.x; acc.y += v0.y + v1.y;
                    acc.z += v0.z + v1.z; acc.w += v0.w + v1.w;
                }
                if (j < hi) {
                    float4 v0 = m4[adj[j] * 32 + lane];
                    acc.x += v0.x; acc.y += v0.y; acc.z += v0.z; acc.w += v0.w;
                }
            }
            uint2 u;
            u.x = packh2(acc.x * ACT_S, acc.y * ACT_S);
            u.y = packh2(acc.z * ACT_S, acc.w * ACT_S);
            *(uint2*)(smem + SM_A + m * PB + lane * 8) = u;
        }
    }
    copy_w(smem, SM_WH, w1h, t);
    copy_w(smem, SM_WL, w1l, t);
    __syncthreads();

    float acc[2][4][4];
    #pragma unroll
    for (int i = 0; i < 2; i++)
        #pragma unroll
        for (int j = 0; j < 4; j++)
            #pragma unroll
            for (int k = 0; k < 4; k++) acc[i][j][k] = 0.f;

    gemm_tile(sb + SM_A, sb + SM_WH, sb + SM_WL, warp_m, warp_n, lane, acc);
    __syncthreads();   // GEMM1 reads of sA/sW done

    // epilogue 1: hidden = relu(acc*ACT_I + b1) -> fp16 (xACT_S) back into A plane
    {
        int l4 = lane >> 2, q = lane & 3;
        #pragma unroll
        for (int mt = 0; mt < 2; mt++)
            #pragma unroll
            for (int nt = 0; nt < 4; nt++) {
                int row = warp_m * 32 + mt * 16 + l4;
                int col = warp_n * 32 + nt * 8 + q * 2;
                float2 b = __ldg((const float2*)&B1[col]);
                #pragma unroll
                for (int h = 0; h < 2; h++) {
                    float v0 = fmaxf(fmaf(acc[mt][nt][2 * h + 0], ACT_I, b.x), 0.f);
                    float v1 = fmaxf(fmaf(acc[mt][nt][2 * h + 1], ACT_I, b.y), 0.f);
                    int r = row + h * 8;
                    *(uint32_t*)(smem + SM_A + r * PB + col * 2) =
                        packh2(v0 * ACT_S, v1 * ACT_S);
                }
            }
    }
    // overwrite W planes with W2 (W1 reads fenced by sync above)
    copy_w(smem, SM_WH, w2h, t);
    copy_w(smem, SM_WL, w2l, t);
    __syncthreads();

    #pragma unroll
    for (int i = 0; i < 2; i++)
        #pragma unroll
        for (int j = 0; j < 4; j++)
            #pragma unroll
            for (int k = 0; k < 4; k++) acc[i][j][k] = 0.f;

    gemm_tile(sb + SM_A, sb + SM_WH, sb + SM_WL, warp_m, warp_n, lane, acc);

    // epilogue 2: out = epi(acc*ACT_I + b2)
    {
        int l4 = lane >> 2, q = lane & 3;
        int stride = (MODE == 3) ? 256 : 128;
        #pragma unroll
        for (int mt = 0; mt < 2; mt++)
            #pragma unroll
            for (int nt = 0; nt < 4; nt++) {
                int col = warp_n * 32 + nt * 8 + q * 2;
                float2 b = __ldg((const float2*)&B2[col]);
                #pragma unroll
                for (int h = 0; h < 2; h++) {
                    int gr = rowBase + warp_m * 32 + mt * 16 + l4 + h * 8;
                    if (gr >= n) continue;
                    float2 v;
                    v.x = fmaf(acc[mt][nt][2 * h + 0], ACT_I, b.x);
                    v.y = fmaf(acc[mt][nt][2 * h + 1], ACT_I, b.y);
                    if (MODE >= 1) { v.x = fmaxf(v.x, 0.f); v.y = fmaxf(v.y, 0.f); }
                    if (MODE >= 2) {
                        if (gr == sink) { v.x = 0.f; v.y = 0.f; }
                        float2 s2 = __ldg((const float2*)&self_t[gr * 128 + col]);
                        v.x += s2.x; v.y += s2.y;
                    }
                    *(float2*)&out[gr * stride + outOfs + col] = v;
                }
            }
    }
}

// ---------------- launch ----------------
extern "C" void kernel_launch(void* const* d_in, const int* in_sizes, int n_in,
                              void* d_out, int out_size)
{
    const float* feat = (const float*)d_in[0];
    const int* src = (const int*)d_in[1];
    const int* dst = (const int*)d_in[2];
    const float* P[20];
    for (int i = 0; i < 20; i++) P[i] = (const float*)d_in[3 + i];
    float* out = (float*)d_out;

    int N = in_sizes[0] / DD;
    int E = in_sizes[1];

    cudaFuncSetAttribute(mma_mlp<0>, cudaFuncAttributeMaxDynamicSharedMemorySize, SMEM_BYTES);
    cudaFuncSetAttribute(mma_mlp<1>, cudaFuncAttributeMaxDynamicSharedMemorySize, SMEM_BYTES);
    cudaFuncSetAttribute(mma_mlp<2>, cudaFuncAttributeMaxDynamicSharedMemorySize, SMEM_BYTES);
    cudaFuncSetAttribute(mma_mlp<3>, cudaFuncAttributeMaxDynamicSharedMemorySize, SMEM_BYTES);

    float *p_self, *p_y, *p_m;
    cudaGetSymbolAddress((void**)&p_self, g_self);
    cudaGetSymbolAddress((void**)&p_y, g_y);
    cudaGetSymbolAddress((void**)&p_m, g_m);
    __half* wbase;
    cudaGetSymbolAddress((void**)&wbase, g_wimg);
    auto wimg = [&](int m, int p) -> const __half* {
        return wbase + (size_t)(m * 2 + p) * DD * DD;
    };

    int gb = (N + BM - 1) / BM;
    int eb = (E + 255) / 256;
    int nb = (N + 255) / 256;

    // CSR for both directions
    zero_cnt_kernel<<<nb, 256>>>(N);
    hist_kernel<<<eb, 256>>>(src, dst, E);
    scan_kernel<<<2, 1024>>>(N);
    place_kernel<<<eb, 256>>>(src, dst, E);

    // weight fp16 hi/lo planes: {nt1,nt2,fp1,fp2,fu1,fu2,bp1,bp2,bu1,bu2}
    WPtrs wp;
    wp.p[0] = P[0];  wp.p[1] = P[2];
    wp.p[2] = P[4];  wp.p[3] = P[6];
    wp.p[4] = P[8];  wp.p[5] = P[10];
    wp.p[6] = P[12]; wp.p[7] = P[14];
    wp.p[8] = P[16]; wp.p[9] = P[18];
    prep_w_kernel<<<(10 * DD * DD + 255) / 256, 256>>>(wp);

    // self_trans = FNN(feat, nt)
    mma_mlp<0><<<gb, 256, SMEM_BYTES>>>(feat, wimg(0, 0), wimg(0, 1), wimg(1, 0), wimg(1, 1),
                                        P[1], P[3], p_self, nullptr, -1, N, 0, 0);

    for (int dir = 0; dir < 2; dir++) {
        int mi1, mi2, ui1, ui2;
        const float *MB1, *MB2, *UB1, *UB2;
        if (dir == 0) { mi1 = 2; mi2 = 3; ui1 = 4; ui2 = 5;
                        MB1 = P[5];  MB2 = P[7];  UB1 = P[9];  UB2 = P[11]; }
        else          { mi1 = 6; mi2 = 7; ui1 = 8; ui2 = 9;
                        MB1 = P[13]; MB2 = P[15]; UB1 = P[17]; UB2 = P[19]; }
        int sink = (dir == 0) ? (N - 1) : 0;
        int ofs = (dir == 0) ? 0 : 128;

        const float* yin = p_self;
        for (int k = 0; k < 3; k++) {
            // per-node message MLP: m = relu(FNN(y))  [FNN(y[src]) == FNN(y)[src]]
            mma_mlp<1><<<gb, 256, SMEM_BYTES>>>(yin, wimg(mi1, 0), wimg(mi1, 1),
                                                wimg(mi2, 0), wimg(mi2, 1),
                                                MB1, MB2, p_m, nullptr, -1, N, 0, 0);
            // fused: z = CSR-gather-sum(m); y/out = relu(FNN(z)) (+self, sink-zero)
            if (k < 2) {
                mma_mlp<2><<<gb, 256, SMEM_BYTES>>>(nullptr, wimg(ui1, 0), wimg(ui1, 1),
                                                    wimg(ui2, 0), wimg(ui2, 1),
                                                    UB1, UB2, p_y, p_self, sink, N, 0, dir);
                yin = p_y;
            } else {
                mma_mlp<3><<<gb, 256, SMEM_BYTES>>>(nullptr, wimg(ui1, 0), wimg(ui1, 1),
                                                    wimg(ui2, 0), wimg(ui2, 1),
                                                    UB1, UB2, out, p_self, sink, N, ofs, dir);
            }
        }
    }
}